// round 14
// baseline (speedup 1.0000x reference)
#include <cuda_runtime.h>
#include <cuda_fp16.h>
#include <cstdint>

// Problem constants (fixed by the dataset)
#define NB 131072   // batch
#define ND 128      // input dim
#define NH 512      // hidden dim
#define NE 2        // experts
#define NO 2        // output dim

#define NCTA 148    // persistent grid (1 CTA per SM; grid barrier is safe)
#define NBLK (NB / 64)    // 2048 route blocks of 64 rows

// ---------------- scratch (device globals; no allocation allowed) ----------
__device__ int g_cnt[NE];        // slot allocator; reset at end of run
__device__ int g_bar;            // grid barrier arrivals
__device__ int g_done;           // end-of-run reset election
__device__ int g_idx[NE][NB];
__device__ __align__(16) __half g_xh[(size_t)NB * 128];   // x fp16, 256B rows

// ---------------- helpers ---------------------------------------------------
__device__ __forceinline__ uint32_t smem_u32(const void* p) {
    uint32_t a;
    asm("{ .reg .u64 t; cvta.to.shared.u64 t, %1; cvt.u32.u64 %0, t; }"
        : "=r"(a) : "l"(p));
    return a;
}
__device__ __forceinline__ uint32_t f16x2(float a, float b) {
    uint32_t u;
    asm("cvt.rn.f16x2.f32 %0, %1, %2;" : "=r"(u) : "f"(b), "f"(a));
    return u;
}
__device__ __forceinline__ void ldsm4(uint32_t* r, uint32_t addr) {
    asm volatile("ldmatrix.sync.aligned.m8n8.x4.shared.b16 {%0,%1,%2,%3}, [%4];"
                 : "=r"(r[0]), "=r"(r[1]), "=r"(r[2]), "=r"(r[3]) : "r"(addr));
}
__device__ __forceinline__ void mma16816(float* d, const uint32_t* a,
                                         uint32_t b0, uint32_t b1) {
    asm volatile(
        "mma.sync.aligned.m16n8k16.row.col.f32.f16.f16.f32 "
        "{%0,%1,%2,%3}, {%4,%5,%6,%7}, {%8,%9}, {%0,%1,%2,%3};"
        : "+f"(d[0]), "+f"(d[1]), "+f"(d[2]), "+f"(d[3])
        : "r"(a[0]), "r"(a[1]), "r"(a[2]), "r"(a[3]), "r"(b0), "r"(b1));
}
__device__ __forceinline__ void cpasync16(uint32_t dst, const void* src) {
    asm volatile("cp.async.cg.shared.global [%0], [%1], 16;"
                 :: "r"(dst), "l"(src) : "memory");
}
#define CP_COMMIT() asm volatile("cp.async.commit_group;" ::: "memory")
#define CP_WAIT0()  asm volatile("cp.async.wait_group 0;" ::: "memory")

__device__ __forceinline__ int ldcg_i(const int* p) {
    int v;
    asm volatile("ld.global.cg.s32 %0, [%1];" : "=r"(v) : "l"(p));
    return v;
}

// ---------------- smem layout ----------------------------------------------
#define PITCH 272
#define ABUF  (128 * PITCH)                 // 34816
#define SM_W    0                           // 512 rows x 272 = 139264
#define SM_A    139264                      // 2 bufs = 69632 (phase0: xs staging)
#define SM_B1   208896                      // 2048
#define SM_W20  210944                      // 2048
#define SM_W21  212992                      // 2048
#define SM_OUT  215040                      // 128*2 floats = 1024
#define SM_PS   216064                      // 1024 (protos fp32, phase 0)
#define SM_HDR  217088                      // 64
#define SM_TOTAL 217152

extern __shared__ __align__(1024) unsigned char smx[];

// ---------------- fused persistent kernel ----------------------------------
__global__ __launch_bounds__(256, 1) void fused_kernel(
    const float* __restrict__ x,  const float* __restrict__ w1,
    const float* __restrict__ b1, const float* __restrict__ w2,
    const float* __restrict__ b2, const float* __restrict__ protos,
    float* __restrict__ out) {

    const int tid = threadIdx.x;
    const int l   = tid & 31;
    const int wd  = tid >> 5;
    const uint32_t smb = smem_u32(smx);

    float* b1s  = (float*)(smx + SM_B1);
    float* w20  = (float*)(smx + SM_W20);
    float* w21  = (float*)(smx + SM_W21);
    float* outb = (float*)(smx + SM_OUT);
    float* ps   = (float*)(smx + SM_PS);
    int*   hdr  = (int*)(smx + SM_HDR);

    // expert this CTA will compute in phase 1
    const int e = ((int)blockIdx.x < NCTA / 2) ? 0 : 1;

    // ================= PHASE 0: route + x fp16 + W1->smem ==================
    ps[tid] = protos[tid];
    outb[tid] = 0.f;

    // W1 fp32 -> fp16 directly into resident smem (L2-broadcast across CTAs)
    {
        const float2* wsrc = (const float2*)w1 + (size_t)e * NH * 64;
        for (int i = tid; i < NH * 64; i += 256) {
            float2 v = wsrc[i];
            *(uint32_t*)(smx + SM_W + (i >> 6) * PITCH + (i & 63) * 4) = f16x2(v.x, v.y);
        }
    }
    // coefficients
    for (int i = tid; i < NH; i += 256) {
        b1s[i] = b1[e * NH + i];
        w20[i] = w2[(e * NO + 0) * NH + i];
        w21[i] = w2[(e * NO + 1) * NH + i];
    }
    const float b2e0 = b2[e * NO + 0], b2e1 = b2[e * NO + 1];
    __syncthreads();

    // route blocks of 64 rows, strided across CTAs (xs staged in SM_A region)
    float* xs = (float*)(smx + SM_A);       // 64 x 132 floats = 33792 B
    for (int blk = blockIdx.x; blk < NBLK; blk += NCTA) {
        const int m0 = blk * 64;

        const float4* x4 = (const float4*)x;
        for (int i = tid; i < 64 * 32; i += 256) {
            int r = i >> 5, c = i & 31;
            float4 v = x4[(size_t)(m0 + r) * 32 + c];
            *(float4*)(&xs[r * 132 + c * 4]) = v;
        }
        __syncthreads();

        int er = 0;
        unsigned m1 = 0;
        if (tid < 64) {
            const float4* xr = (const float4*)(&xs[tid * 132]);
            const float4* p0 = (const float4*)(&ps[0]);
            const float4* p1 = (const float4*)(&ps[128]);
            float d0 = 0.f, d1 = 0.f;
            #pragma unroll
            for (int j = 0; j < 32; j++) {
                float4 xv = xr[j]; float4 a = p0[j]; float4 b = p1[j];
                float t;
                t = xv.x - a.x; d0 += t * t;   t = xv.y - a.y; d0 += t * t;
                t = xv.z - a.z; d0 += t * t;   t = xv.w - a.w; d0 += t * t;
                t = xv.x - b.x; d1 += t * t;   t = xv.y - b.y; d1 += t * t;
                t = xv.z - b.z; d1 += t * t;   t = xv.w - b.w; d1 += t * t;
            }
            er = (d1 < d0) ? 1 : 0;            // tie -> 0 (argmin picks first)
            m1 = __ballot_sync(0xffffffffu, er);
            if (l == 0) hdr[4 + wd] = __popc(m1);
        }

        // fp16 conversion of staged rows (all threads; overlaps distance calc)
        for (int i = tid; i < 64 * 32; i += 256) {
            int r = i >> 5, c = i & 31;
            float4 v = *(float4*)(&xs[r * 132 + c * 4]);
            uint2 u = make_uint2(f16x2(v.x, v.y), f16x2(v.z, v.w));
            ((uint2*)g_xh)[(size_t)(m0 + r) * 32 + c] = u;
        }
        __syncthreads();

        if (tid == 0) {
            int tot1 = hdr[4] + hdr[5];
            hdr[6] = atomicAdd(&g_cnt[0], 64 - tot1);
            hdr[7] = atomicAdd(&g_cnt[1], tot1);
        }
        __syncthreads();

        if (tid < 64) {
            int r1   = __popc(m1 & ((1u << l) - 1u));
            int rank = er ? r1 : (l - r1);
            int pre1 = (wd == 1) ? hdr[4] : 0;
            int pre0 = wd * 32 - pre1;
            int slot = er ? (hdr[7] + pre1 + rank) : (hdr[6] + pre0 + rank);
            g_idx[er][slot] = m0 + tid;
        }
        __syncthreads();
    }

    // ================= GRID BARRIER ========================================
    __threadfence();
    __syncthreads();
    if (tid == 0) {
        asm volatile("red.global.add.s32 [%0], 1;" :: "l"(&g_bar) : "memory");
        while (ldcg_i(&g_bar) < NCTA) __nanosleep(64);
        hdr[0] = ldcg_i(&g_cnt[0]);
        hdr[1] = ldcg_i(&g_cnt[1]);
    }
    __syncthreads();
    const int c0 = hdr[0], c1 = hdr[1];

    // ================= PHASE 1: persistent HMMA (round-8 geometry) =========
    const int t0 = (c0 + 127) >> 7, t1 = (c1 + 127) >> 7;
    const int T = t0 + t1;
    int n0c;
    if (t1 == 0)      n0c = NCTA;
    else if (t0 == 0) n0c = 0;
    else {
        n0c = (int)((long long)NCTA * t0 / T);
        if (n0c < 1) n0c = 1;
        if (n0c > NCTA - 1) n0c = NCTA - 1;
    }
    // NOTE: expert assignment must match phase-0 (e by blockIdx < NCTA/2).
    // Use e fixed; tile split among the CTAs owning this expert.
    const int nown  = e ? (NCTA - NCTA / 2) : (NCTA / 2);
    const int owni  = e ? ((int)blockIdx.x - NCTA / 2) : (int)blockIdx.x;
    const int tcnt  = e ? t1 : t0;
    const int cnt   = e ? c1 : c0;
    (void)n0c;
    const int ntiles = (owni < tcnt) ? (tcnt - 1 - owni) / nown + 1 : 0;

    if (ntiles > 0) {
        // per-lane fragment addressing (4m x 2n, warp tile m32 x n64)
        const int wm = wd & 3;
        const int wn = wd >> 2;
        uint32_t aRel0, aRel1;
        {
            int mrow = wm * 32 + (l & 7) + ((l >> 3) & 1) * 8;
            int koff = (l >= 16) ? 16 : 0;
            aRel0 = (uint32_t)(mrow * PITCH + koff);
            aRel1 = aRel0 + 16 * PITCH;
        }
        uint32_t bOff[4];
        {
            int nr   = (l & 7) + ((l >= 16) ? 8 : 0);
            int koff = ((l >> 3) & 1) * 16;
            #pragma unroll
            for (int nj = 0; nj < 4; nj++)
                bOff[nj] = (uint32_t)((wn * 64 + nj * 16 + nr) * PITCH + koff);
        }

        auto prefetchA = [&](int posbase, int buf) {
            const int row = tid >> 1, segb = (tid & 1) * 8;
            int pos = posbase + row;
            int gi = ldcg_i(&g_idx[e][(pos < cnt) ? pos : posbase]);
            const char* src = (const char*)g_xh + (size_t)gi * 256 + segb * 16;
            uint32_t dst = smb + SM_A + buf * ABUF + row * PITCH + segb * 16;
            #pragma unroll
            for (int j = 0; j < 8; j++) cpasync16(dst + j * 16, src + j * 16);
            CP_COMMIT();
        };

        prefetchA(owni * 128, 0);
        CP_WAIT0();
        __syncthreads();

        int p = 0;
        for (int it = 0; it < ntiles; it++) {
            const int posbase = (owni + it * nown) * 128;
            if (it + 1 < ntiles) prefetchA((owni + (it + 1) * nown) * 128, p ^ 1);

            const uint32_t abase = smb + SM_A + p * ABUF;
            uint32_t areg[8][2][4];
            #pragma unroll
            for (int ks = 0; ks < 8; ks++) {
                ldsm4(areg[ks][0], abase + aRel0 + ks * 32);
                ldsm4(areg[ks][1], abase + aRel1 + ks * 32);
            }

            float o0[4] = {0.f, 0.f, 0.f, 0.f};
            float o1[4] = {0.f, 0.f, 0.f, 0.f};

            #pragma unroll
            for (int nt = 0; nt < 4; nt++) {
                float acc[2][8][4];
                #pragma unroll
                for (int mi = 0; mi < 2; mi++)
                    #pragma unroll
                    for (int ni = 0; ni < 8; ni++)
                        #pragma unroll
                        for (int c = 0; c < 4; c++) acc[mi][ni][c] = 0.f;

                const uint32_t wbase = smb + SM_W + nt * 128 * PITCH;
                #pragma unroll
                for (int ks = 0; ks < 8; ks++) {
                    const int off = ks * 32;
                    uint32_t b[4][4];
                    #pragma unroll
                    for (int nj = 0; nj < 4; nj++)
                        ldsm4(b[nj], wbase + bOff[nj] + off);
                    #pragma unroll
                    for (int mi = 0; mi < 2; mi++)
                        #pragma unroll
                        for (int nj = 0; nj < 4; nj++) {
                            mma16816(acc[mi][2 * nj],     areg[ks][mi], b[nj][0], b[nj][1]);
                            mma16816(acc[mi][2 * nj + 1], areg[ks][mi], b[nj][2], b[nj][3]);
                        }
                }

                const int hbase = nt * 128 + wn * 64 + 2 * (l & 3);
                #pragma unroll
                for (int ni = 0; ni < 8; ni++) {
                    const int h = hbase + ni * 8;
                    float bq0 = b1s[h],   bq1 = b1s[h + 1];
                    float p00 = w20[h],   p01 = w20[h + 1];
                    float p10 = w21[h],   p11 = w21[h + 1];
                    #pragma unroll
                    for (int mi = 0; mi < 2; mi++)
                        #pragma unroll
                        for (int c = 0; c < 4; c++) {
                            float v = acc[mi][ni][c] + ((c & 1) ? bq1 : bq0);
                            v = fmaxf(v, 0.f);
                            int s = mi * 2 + (c >> 1);
                            o0[s] = fmaf(v, (c & 1) ? p01 : p00, o0[s]);
                            o1[s] = fmaf(v, (c & 1) ? p11 : p10, o1[s]);
                        }
                }
            }

            // quad reduce, cross-n-warp via smem atomics (round-8 epilogue)
            #pragma unroll
            for (int s = 0; s < 4; s++) {
                o0[s] += __shfl_xor_sync(0xffffffffu, o0[s], 1);
                o0[s] += __shfl_xor_sync(0xffffffffu, o0[s], 2);
                o1[s] += __shfl_xor_sync(0xffffffffu, o1[s], 1);
                o1[s] += __shfl_xor_sync(0xffffffffu, o1[s], 2);
            }
            if ((l & 3) == 0) {
                #pragma unroll
                for (int s = 0; s < 4; s++) {
                    int row = wm * 32 + (s >> 1) * 16 + (s & 1) * 8 + (l >> 2);
                    atomicAdd(&outb[row * 2 + 0], o0[s]);
                    atomicAdd(&outb[row * 2 + 1], o1[s]);
                }
            }
            __syncthreads();

            if (tid < 128) {
                int pos = posbase + tid;
                if (pos < cnt) {
                    int gi = ldcg_i(&g_idx[e][pos]);
                    out[(size_t)gi * 2 + 0] = outb[tid * 2 + 0] + b2e0;
                    out[(size_t)gi * 2 + 1] = outb[tid * 2 + 1] + b2e1;
                }
                outb[tid * 2 + 0] = 0.f;     // reader zeroes what it read
                outb[tid * 2 + 1] = 0.f;
            }

            CP_WAIT0();
            __syncthreads();
            p ^= 1;
        }
    }

    // ================= end-of-run reset (graph-replay determinism) ==========
    __threadfence();
    __syncthreads();
    if (tid == 0) {
        int old = atomicAdd(&g_done, 1);
        if (old == NCTA - 1) {
            g_cnt[0] = 0; g_cnt[1] = 0;
            g_bar = 0; g_done = 0;
        }
    }
}

// ---------------- launch ----------------------------------------------------
extern "C" void kernel_launch(void* const* d_in, const int* in_sizes, int n_in,
                              void* d_out, int out_size) {
    const float* x      = (const float*)d_in[0];
    const float* w1     = (const float*)d_in[1];
    const float* b1     = (const float*)d_in[2];
    const float* w2     = (const float*)d_in[3];
    const float* b2     = (const float*)d_in[4];
    const float* protos = (const float*)d_in[5];
    float* out = (float*)d_out;

    static int smem_set = 0;
    if (!smem_set) {
        cudaFuncSetAttribute(fused_kernel, cudaFuncAttributeMaxDynamicSharedMemorySize,
                             SM_TOTAL);
        smem_set = 1;
    }

    fused_kernel<<<NCTA, 256, SM_TOTAL>>>(x, w1, b1, w2, b2, protos, out);
}

// round 15
// speedup vs baseline: 1.9159x; 1.9159x over previous
#include <cuda_runtime.h>
#include <cuda_fp16.h>
#include <cstdint>

// Problem constants (fixed by the dataset)
#define NB 131072   // batch
#define ND 128      // input dim
#define NH 512      // hidden dim
#define NE 2        // experts
#define NO 2        // output dim

#define NCTA 148    // persistent grid
#define RBLK (NB / 64)    // 2048 route blocks

// ---------------- scratch (device globals; no allocation allowed) ----------
__device__ int g_cnt[NE];        // zero at start; reset by mma at end of run
__device__ int g_done;           // arrival counter for end-of-run reset
__device__ int g_idx[NE][NB];
__device__ __align__(16) __half g_w1c[NE * NH * 128];      // W1 fp16, 256B rows
__device__ __align__(16) __half g_xh[(size_t)NB * 128];    // x fp16, 256B rows

// ---------------- helpers ---------------------------------------------------
__device__ __forceinline__ uint32_t smem_u32(const void* p) {
    uint32_t a;
    asm("{ .reg .u64 t; cvta.to.shared.u64 t, %1; cvt.u32.u64 %0, t; }"
        : "=r"(a) : "l"(p));
    return a;
}
__device__ __forceinline__ uint32_t f16x2(float a, float b) {
    uint32_t u;
    asm("cvt.rn.f16x2.f32 %0, %1, %2;" : "=r"(u) : "f"(b), "f"(a));
    return u;
}
__device__ __forceinline__ void ldsm4(uint32_t* r, uint32_t addr) {
    asm volatile("ldmatrix.sync.aligned.m8n8.x4.shared.b16 {%0,%1,%2,%3}, [%4];"
                 : "=r"(r[0]), "=r"(r[1]), "=r"(r[2]), "=r"(r[3]) : "r"(addr));
}
__device__ __forceinline__ void mma16816(float* d, const uint32_t* a,
                                         uint32_t b0, uint32_t b1) {
    asm volatile(
        "mma.sync.aligned.m16n8k16.row.col.f32.f16.f16.f32 "
        "{%0,%1,%2,%3}, {%4,%5,%6,%7}, {%8,%9}, {%0,%1,%2,%3};"
        : "+f"(d[0]), "+f"(d[1]), "+f"(d[2]), "+f"(d[3])
        : "r"(a[0]), "r"(a[1]), "r"(a[2]), "r"(a[3]), "r"(b0), "r"(b1));
}
__device__ __forceinline__ void cpasync16(uint32_t dst, const void* src) {
    asm volatile("cp.async.cg.shared.global [%0], [%1], 16;"
                 :: "r"(dst), "l"(src) : "memory");
}
#define CP_COMMIT() asm volatile("cp.async.commit_group;" ::: "memory")
#define CP_WAIT0()  asm volatile("cp.async.wait_group 0;" ::: "memory")

// ---------------- kernel 1: routing + x fp16 + W1 fp16 ---------------------
// blocks [0,RBLK): 64 rows each, smem-staged (coalesced); ballot ranking.
// blocks [RBLK,RBLK+256): convert W1 -> g_w1c
__global__ __launch_bounds__(256) void route_kernel(const float* __restrict__ x,
                                                    const float* __restrict__ protos,
                                                    const float* __restrict__ w1) {
    const int tid = threadIdx.x;

    if (blockIdx.x >= RBLK) {              // ---- W1 convert tail blocks ----
        int i = (blockIdx.x - RBLK) * 256 + tid;    // over NE*NH*64 float2
        float2 v = reinterpret_cast<const float2*>(w1)[i];
        reinterpret_cast<uint32_t*>(g_w1c)[i] = f16x2(v.x, v.y);
        return;
    }

    __shared__ float xs[64 * 132];
    __shared__ float ps[256];
    __shared__ int   wcnt_sh[2];
    __shared__ int   base_sh[2];

    const int m0 = blockIdx.x * 64;
    if (tid < 256) ps[tid] = protos[tid];

    const float4* x4 = reinterpret_cast<const float4*>(x);
    for (int i = tid; i < 64 * 32; i += 256) {
        int r = i >> 5, c = i & 31;
        float4 v = x4[(size_t)(m0 + r) * 32 + c];
        *reinterpret_cast<float4*>(&xs[r * 132 + c * 4]) = v;
    }
    __syncthreads();

    int e = 0;
    unsigned m1 = 0;
    const int l = tid & 31, wd = tid >> 5;
    if (tid < 64) {
        const float4* xr = reinterpret_cast<const float4*>(&xs[tid * 132]);
        const float4* p0 = reinterpret_cast<const float4*>(&ps[0]);
        const float4* p1 = reinterpret_cast<const float4*>(&ps[128]);
        float d0 = 0.f, d1 = 0.f;
        #pragma unroll
        for (int j = 0; j < 32; j++) {
            float4 xv = xr[j]; float4 a = p0[j]; float4 b = p1[j];
            float t;
            t = xv.x - a.x; d0 += t * t;   t = xv.y - a.y; d0 += t * t;
            t = xv.z - a.z; d0 += t * t;   t = xv.w - a.w; d0 += t * t;
            t = xv.x - b.x; d1 += t * t;   t = xv.y - b.y; d1 += t * t;
            t = xv.z - b.z; d1 += t * t;   t = xv.w - b.w; d1 += t * t;
        }
        e = (d1 < d0) ? 1 : 0;             // tie -> 0 (argmin picks first)
        m1 = __ballot_sync(0xffffffffu, e);
        if (l == 0) wcnt_sh[wd] = __popc(m1);
    }

    // fp16 conversion of the staged rows (all 256 threads, overlaps distances)
    for (int i = tid; i < 64 * 32; i += 256) {
        int r = i >> 5, c = i & 31;
        float4 v = *reinterpret_cast<float4*>(&xs[r * 132 + c * 4]);
        uint2 u = make_uint2(f16x2(v.x, v.y), f16x2(v.z, v.w));
        reinterpret_cast<uint2*>(g_xh)[(size_t)(m0 + r) * 32 + c] = u;
    }
    __syncthreads();

    if (tid == 0) {
        int tot1 = wcnt_sh[0] + wcnt_sh[1];
        base_sh[0] = atomicAdd(&g_cnt[0], 64 - tot1);
        base_sh[1] = atomicAdd(&g_cnt[1], tot1);
    }
    __syncthreads();

    if (tid < 64) {
        int r1   = __popc(m1 & ((1u << l) - 1u));
        int rank = e ? r1 : (l - r1);
        int pre1 = (wd == 1) ? wcnt_sh[0] : 0;
        int pre0 = wd * 32 - pre1;
        int slot = e ? (base_sh[1] + pre1 + rank) : (base_sh[0] + pre0 + rank);
        g_idx[e][slot] = m0 + tid;
    }
}

// ---------------- kernel 2: persistent HMMA GEMM + fused epilogue ----------
// 148 CTAs x 256 threads (8 warps = 4m x 2n, warp tile m32 x n64 — the
// fastest measured geometry, 63.1us). Full W1 staged once; A tiles
// double-buffered via cp.async; A frags in regs across n-passes;
// round-8 smem-atomic epilogue (fastest measured).
#define PITCH 272
#define ABUF  (128 * PITCH)                 // 34816
#define SM_W    0                           // 512 rows -> 139264
#define SM_A    (512 * PITCH)               // 139264, 2 bufs
#define SM_B1   (SM_A + 2 * ABUF)           // 208896
#define SM_W20  (SM_B1 + 2048)              // 210944
#define SM_W21  (SM_W20 + 2048)             // 212992
#define SM_OUT  (SM_W21 + 2048)             // 215040  128*2 floats
#define SM_HDR  (SM_OUT + 1024)             // 216064
#define SM_TOTAL (SM_HDR + 64)              // 216128 bytes

extern __shared__ __align__(1024) unsigned char sm_mma[];

__global__ __launch_bounds__(256, 1) void mma_kernel(
    const float* __restrict__ b1, const float* __restrict__ w2,
    const float* __restrict__ b2, float* __restrict__ out) {

    const int tid = threadIdx.x;
    int* hdr = (int*)(sm_mma + SM_HDR);

    // read counts once; end-of-run reset by the last arriving CTA
    if (tid == 0) {
        int c0 = g_cnt[0], c1 = g_cnt[1];
        hdr[0] = c0; hdr[1] = c1;
        unsigned dep = ((unsigned)(c0 | c1)) >> 31;     // 0, but data-dependent
        int old = atomicAdd(&g_done, 1 + (int)dep);
        if (old == NCTA - 1) { g_cnt[0] = 0; g_cnt[1] = 0; g_done = 0; }
    }
    __syncthreads();
    const int c0 = hdr[0], c1 = hdr[1];

    const int t0 = (c0 + 127) >> 7, t1 = (c1 + 127) >> 7;
    const int T = t0 + t1;
    int n0c;
    if (t1 == 0)      n0c = NCTA;
    else if (t0 == 0) n0c = 0;
    else {
        n0c = (int)((long long)NCTA * t0 / T);
        if (n0c < 1) n0c = 1;
        if (n0c > NCTA - 1) n0c = NCTA - 1;
    }

    int e, tbase, tstride, tcnt, cnt;
    if ((int)blockIdx.x < n0c) { e = 0; tbase = blockIdx.x;        tstride = n0c;        tcnt = t0; cnt = c0; }
    else                       { e = 1; tbase = blockIdx.x - n0c;  tstride = NCTA - n0c; tcnt = t1; cnt = c1; }
    const int ntiles = (tbase < tcnt) ? (tcnt - 1 - tbase) / tstride + 1 : 0;
    if (ntiles == 0) return;

    const uint32_t smb = smem_u32(sm_mma);
    float* b1s  = (float*)(sm_mma + SM_B1);
    float* w20  = (float*)(sm_mma + SM_W20);
    float* w21  = (float*)(sm_mma + SM_W21);
    float* outb = (float*)(sm_mma + SM_OUT);

    // ---- A-tile prefetch: 256B fp16 rows from g_xh, 2 threads per row ------
    auto prefetchA = [&](int posbase, int buf) {
        const int row = tid >> 1, segb = (tid & 1) * 8;
        int pos = posbase + row;
        int gi = g_idx[e][(pos < cnt) ? pos : posbase];
        const char* src = (const char*)g_xh + (size_t)gi * 256 + segb * 16;
        uint32_t dst = smb + SM_A + buf * ABUF + row * PITCH + segb * 16;
        #pragma unroll
        for (int j = 0; j < 8; j++) cpasync16(dst + j * 16, src + j * 16);
        CP_COMMIT();
    };

    // ---- prologue: A(tile0) + full W stage + coefficients ------------------
    prefetchA(tbase * 128, 0);
    {
        const char* wsrc = (const char*)(g_w1c + (size_t)e * NH * 128);
        #pragma unroll
        for (int k = 0; k < 32; k++) {                 // 8192 x 16B
            int i = tid + k * 256;
            int row = i >> 4, seg = i & 15;
            cpasync16(smb + SM_W + row * PITCH + seg * 16, wsrc + row * 256 + seg * 16);
        }
        CP_COMMIT();
    }
    for (int i = tid; i < NH; i += 256) {
        b1s[i] = b1[e * NH + i];
        w20[i] = w2[(e * NO + 0) * NH + i];
        w21[i] = w2[(e * NO + 1) * NH + i];
    }
    if (tid < 256) { outb[tid] = 0.f; }
    const float b2e0 = b2[e * NO + 0], b2e1 = b2[e * NO + 1];

    CP_WAIT0();
    __syncthreads();

    // ---- per-lane fragment addressing (4m x 2n, warp tile m32 x n64) -------
    const int l  = tid & 31;
    const int w  = tid >> 5;
    const int wm = w & 3;       // m group (32 rows)
    const int wn = w >> 2;      // n half (64 cols)

    uint32_t aRel0, aRel1;
    {
        int mrow = wm * 32 + (l & 7) + ((l >> 3) & 1) * 8;
        int koff = (l >= 16) ? 16 : 0;
        aRel0 = (uint32_t)(mrow * PITCH + koff);
        aRel1 = aRel0 + 16 * PITCH;
    }
    uint32_t bOff[4];
    {
        int nr   = (l & 7) + ((l >= 16) ? 8 : 0);
        int koff = ((l >> 3) & 1) * 16;
        #pragma unroll
        for (int nj = 0; nj < 4; nj++)
            bOff[nj] = (uint32_t)((wn * 64 + nj * 16 + nr) * PITCH + koff);
    }

    // ---- persistent tile loop ----------------------------------------------
    int p = 0;
    for (int it = 0; it < ntiles; it++) {
        const int posbase = (tbase + it * tstride) * 128;
        if (it + 1 < ntiles) prefetchA((tbase + (it + 1) * tstride) * 128, p ^ 1);

        // A fragments: m32 x k128, loaded once, reused across all 4 n-passes
        const uint32_t abase = smb + SM_A + p * ABUF;
        uint32_t areg[8][2][4];
        #pragma unroll
        for (int ks = 0; ks < 8; ks++) {
            ldsm4(areg[ks][0], abase + aRel0 + ks * 32);
            ldsm4(areg[ks][1], abase + aRel1 + ks * 32);
        }

        float o0[4] = {0.f, 0.f, 0.f, 0.f};
        float o1[4] = {0.f, 0.f, 0.f, 0.f};

        #pragma unroll
        for (int nt = 0; nt < 4; nt++) {
            float acc[2][8][4];
            #pragma unroll
            for (int mi = 0; mi < 2; mi++)
                #pragma unroll
                for (int ni = 0; ni < 8; ni++)
                    #pragma unroll
                    for (int c = 0; c < 4; c++) acc[mi][ni][c] = 0.f;

            const uint32_t wbase = smb + SM_W + nt * 128 * PITCH;
            #pragma unroll
            for (int ks = 0; ks < 8; ks++) {
                const int off = ks * 32;
                uint32_t b[4][4];
                #pragma unroll
                for (int nj = 0; nj < 4; nj++)
                    ldsm4(b[nj], wbase + bOff[nj] + off);
                #pragma unroll
                for (int mi = 0; mi < 2; mi++)
                    #pragma unroll
                    for (int nj = 0; nj < 4; nj++) {
                        mma16816(acc[mi][2 * nj],     areg[ks][mi], b[nj][0], b[nj][1]);
                        mma16816(acc[mi][2 * nj + 1], areg[ks][mi], b[nj][2], b[nj][3]);
                    }
            }

            // fused epilogue: +b1, relu, *W2 -> per-lane partials (no barrier)
            const int hbase = nt * 128 + wn * 64 + 2 * (l & 3);
            #pragma unroll
            for (int ni = 0; ni < 8; ni++) {
                const int h = hbase + ni * 8;
                float bq0 = b1s[h],   bq1 = b1s[h + 1];
                float p00 = w20[h],   p01 = w20[h + 1];
                float p10 = w21[h],   p11 = w21[h + 1];
                #pragma unroll
                for (int mi = 0; mi < 2; mi++)
                    #pragma unroll
                    for (int c = 0; c < 4; c++) {
                        float v = acc[mi][ni][c] + ((c & 1) ? bq1 : bq0);
                        v = fmaxf(v, 0.f);
                        int s = mi * 2 + (c >> 1);
                        o0[s] = fmaf(v, (c & 1) ? p01 : p00, o0[s]);
                        o1[s] = fmaf(v, (c & 1) ? p11 : p10, o1[s]);
                    }
            }
        }

        // quad reduce (cols live on l&3), cross-n-warp via smem atomics
        #pragma unroll
        for (int s = 0; s < 4; s++) {
            o0[s] += __shfl_xor_sync(0xffffffffu, o0[s], 1);
            o0[s] += __shfl_xor_sync(0xffffffffu, o0[s], 2);
            o1[s] += __shfl_xor_sync(0xffffffffu, o1[s], 1);
            o1[s] += __shfl_xor_sync(0xffffffffu, o1[s], 2);
        }
        if ((l & 3) == 0) {
            #pragma unroll
            for (int s = 0; s < 4; s++) {
                int row = wm * 32 + (s >> 1) * 16 + (s & 1) * 8 + (l >> 2);
                atomicAdd(&outb[row * 2 + 0], o0[s]);
                atomicAdd(&outb[row * 2 + 1], o1[s]);
            }
        }
        __syncthreads();

        if (tid < 128) {
            int pos = posbase + tid;
            if (pos < cnt) {
                int gi = g_idx[e][pos];
                out[(size_t)gi * 2 + 0] = outb[tid * 2 + 0] + b2e0;
                out[(size_t)gi * 2 + 1] = outb[tid * 2 + 1] + b2e1;
            }
            outb[tid * 2 + 0] = 0.f;     // reader zeroes what it read (no race)
            outb[tid * 2 + 1] = 0.f;
        }

        CP_WAIT0();          // next A tile resident
        __syncthreads();     // outb reset + A buffer handoff visible to all
        p ^= 1;
    }
}

// ---------------- launch ----------------------------------------------------
extern "C" void kernel_launch(void* const* d_in, const int* in_sizes, int n_in,
                              void* d_out, int out_size) {
    const float* x      = (const float*)d_in[0];
    const float* w1     = (const float*)d_in[1];
    const float* b1     = (const float*)d_in[2];
    const float* w2     = (const float*)d_in[3];
    const float* b2     = (const float*)d_in[4];
    const float* protos = (const float*)d_in[5];
    float* out = (float*)d_out;

    static int smem_set = 0;
    if (!smem_set) {
        cudaFuncSetAttribute(mma_kernel, cudaFuncAttributeMaxDynamicSharedMemorySize,
                             SM_TOTAL);
        smem_set = 1;
    }

    route_kernel<<<RBLK + 256, 256>>>(x, protos, w1);   // route + x fp16 + W1 fp16
    mma_kernel<<<NCTA, 256, SM_TOTAL>>>(b1, w2, b2, out);
}

// round 16
// speedup vs baseline: 1.9493x; 1.0174x over previous
#include <cuda_runtime.h>
#include <cuda_fp16.h>
#include <cstdint>

// Problem constants (fixed by the dataset)
#define NB 131072   // batch
#define ND 128      // input dim
#define NH 512      // hidden dim
#define NE 2        // experts
#define NO 2        // output dim

#define NCTA 148    // persistent grid
#define RB2  512    // route blocks (256 rows each)

// ---------------- scratch (device globals; no allocation allowed) ----------
__device__ int g_cnt[NE];        // zero at start; reset by mma at end of run
__device__ int g_done;           // arrival counter for end-of-run reset
__device__ int g_idx[NE][NB];
__device__ __align__(16) __half g_w1c[NE * NH * 128];      // W1 fp16, 256B rows
__device__ __align__(16) __half g_xh[(size_t)NB * 128];    // x fp16, 256B rows

// ---------------- helpers ---------------------------------------------------
__device__ __forceinline__ uint32_t smem_u32(const void* p) {
    uint32_t a;
    asm("{ .reg .u64 t; cvta.to.shared.u64 t, %1; cvt.u32.u64 %0, t; }"
        : "=r"(a) : "l"(p));
    return a;
}
__device__ __forceinline__ uint32_t f16x2(float a, float b) {
    uint32_t u;
    asm("cvt.rn.f16x2.f32 %0, %1, %2;" : "=r"(u) : "f"(b), "f"(a));
    return u;
}
__device__ __forceinline__ void ldsm4(uint32_t* r, uint32_t addr) {
    asm volatile("ldmatrix.sync.aligned.m8n8.x4.shared.b16 {%0,%1,%2,%3}, [%4];"
                 : "=r"(r[0]), "=r"(r[1]), "=r"(r[2]), "=r"(r[3]) : "r"(addr));
}
__device__ __forceinline__ void mma16816(float* d, const uint32_t* a,
                                         uint32_t b0, uint32_t b1) {
    asm volatile(
        "mma.sync.aligned.m16n8k16.row.col.f32.f16.f16.f32 "
        "{%0,%1,%2,%3}, {%4,%5,%6,%7}, {%8,%9}, {%0,%1,%2,%3};"
        : "+f"(d[0]), "+f"(d[1]), "+f"(d[2]), "+f"(d[3])
        : "r"(a[0]), "r"(a[1]), "r"(a[2]), "r"(a[3]), "r"(b0), "r"(b1));
}
__device__ __forceinline__ void cpasync16(uint32_t dst, const void* src) {
    asm volatile("cp.async.cg.shared.global [%0], [%1], 16;"
                 :: "r"(dst), "l"(src) : "memory");
}
#define CP_COMMIT() asm volatile("cp.async.commit_group;" ::: "memory")
#define CP_WAIT0()  asm volatile("cp.async.wait_group 0;" ::: "memory")

// ---------------- kernel 1: routing + x fp16 + W1 fp16 ---------------------
// blocks [0,RB2): 256 rows each, register-direct quad-per-row pipeline —
// distances + fp16 emit in ONE pass over x, no smem data staging.
// blocks [RB2,RB2+256): convert W1 -> g_w1c
__global__ __launch_bounds__(256) void route_kernel(const float* __restrict__ x,
                                                    const float* __restrict__ protos,
                                                    const float* __restrict__ w1) {
    const int tid = threadIdx.x;

    if (blockIdx.x >= RB2) {               // ---- W1 convert tail blocks ----
        int i = (blockIdx.x - RB2) * 256 + tid;     // over NE*NH*64 float2
        float2 v = reinterpret_cast<const float2*>(w1)[i];
        reinterpret_cast<uint32_t*>(g_w1c)[i] = f16x2(v.x, v.y);
        return;
    }

    __shared__ float ps[256];
    __shared__ int   wcnt[8];
    __shared__ int   base_sh[2];

    ps[tid] = protos[tid];
    __syncthreads();

    const int l  = tid & 31, wd = tid >> 5;
    const int q  = l >> 2;          // quad id: row within group of 8
    const int j4 = l & 3;           // lane within quad
    const int wbase = (blockIdx.x * 8 + wd) * 32;   // 32 rows per warp

    const float4* p0 = reinterpret_cast<const float4*>(ps);
    const float4* p1 = p0 + 32;

    unsigned m_e[4];
    #pragma unroll
    for (int i = 0; i < 4; i++) {
        const int row = wbase + i * 8 + q;
        const float4* xr = reinterpret_cast<const float4*>(x) + (size_t)row * 32;
        uint2* xo = reinterpret_cast<uint2*>(g_xh) + (size_t)row * 32;
        float d0 = 0.f, d1 = 0.f;
        #pragma unroll
        for (int c = 0; c < 8; c++) {
            float4 v = xr[j4 + c * 4];
            float4 a = p0[j4 + c * 4];
            float4 b = p1[j4 + c * 4];
            float t;
            t = v.x - a.x; d0 += t * t;   t = v.y - a.y; d0 += t * t;
            t = v.z - a.z; d0 += t * t;   t = v.w - a.w; d0 += t * t;
            t = v.x - b.x; d1 += t * t;   t = v.y - b.y; d1 += t * t;
            t = v.z - b.z; d1 += t * t;   t = v.w - b.w; d1 += t * t;
            xo[j4 + c * 4] = make_uint2(f16x2(v.x, v.y), f16x2(v.z, v.w));
        }
        d0 += __shfl_xor_sync(0xffffffffu, d0, 1);
        d0 += __shfl_xor_sync(0xffffffffu, d0, 2);
        d1 += __shfl_xor_sync(0xffffffffu, d1, 1);
        d1 += __shfl_xor_sync(0xffffffffu, d1, 2);
        const int er = (d1 < d0) ? 1 : 0;          // tie -> 0 (argmin first)
        m_e[i] = __ballot_sync(0xffffffffu, (j4 == 0) && er);
    }

    int k1 = 0;
    #pragma unroll
    for (int i = 0; i < 4; i++) k1 += __popc(m_e[i]);
    if (l == 0) wcnt[wd] = k1;
    __syncthreads();

    if (tid == 0) {
        int tot1 = 0;
        #pragma unroll
        for (int i = 0; i < 8; i++) tot1 += wcnt[i];
        base_sh[0] = atomicAdd(&g_cnt[0], 256 - tot1);
        base_sh[1] = atomicAdd(&g_cnt[1], tot1);
    }
    __syncthreads();

    if (j4 == 0) {                  // 8 leader lanes scatter the warp's rows
        int pre1 = 0;
        #pragma unroll
        for (int i = 0; i < 8; i++) pre1 += (i < wd) ? wcnt[i] : 0;
        const int pre0 = wd * 32 - pre1;
        const unsigned lowmask = (1u << l) - 1u;
        int run0 = 0, run1 = 0;
        #pragma unroll
        for (int i = 0; i < 4; i++) {
            const int cnt1 = __popc(m_e[i]);
            const int ei   = (m_e[i] >> l) & 1;
            const int lo1  = __popc(m_e[i] & lowmask);
            const int lo0  = q - lo1;
            const int slot = ei ? (base_sh[1] + pre1 + run1 + lo1)
                                : (base_sh[0] + pre0 + run0 + lo0);
            g_idx[ei][slot] = wbase + i * 8 + q;
            run1 += cnt1;
            run0 += 8 - cnt1;
        }
    }
}

// ---------------- kernel 2: persistent HMMA GEMM + fused epilogue ----------
// UNCHANGED from the 84.1us best: 148 CTAs x 256 threads (8 warps = 4m x 2n,
// warp tile m32 x n64, 63.7us measured = ~96% of legacy-HMMA floor).
#define PITCH 272
#define ABUF  (128 * PITCH)                 // 34816
#define SM_W    0                           // 512 rows -> 139264
#define SM_A    (512 * PITCH)               // 139264, 2 bufs
#define SM_B1   (SM_A + 2 * ABUF)           // 208896
#define SM_W20  (SM_B1 + 2048)              // 210944
#define SM_W21  (SM_W20 + 2048)             // 212992
#define SM_OUT  (SM_W21 + 2048)             // 215040  128*2 floats
#define SM_HDR  (SM_OUT + 1024)             // 216064
#define SM_TOTAL (SM_HDR + 64)              // 216128 bytes

extern __shared__ __align__(1024) unsigned char sm_mma[];

__global__ __launch_bounds__(256, 1) void mma_kernel(
    const float* __restrict__ b1, const float* __restrict__ w2,
    const float* __restrict__ b2, float* __restrict__ out) {

    const int tid = threadIdx.x;
    int* hdr = (int*)(sm_mma + SM_HDR);

    // read counts once; end-of-run reset by the last arriving CTA
    if (tid == 0) {
        int c0 = g_cnt[0], c1 = g_cnt[1];
        hdr[0] = c0; hdr[1] = c1;
        unsigned dep = ((unsigned)(c0 | c1)) >> 31;     // 0, but data-dependent
        int old = atomicAdd(&g_done, 1 + (int)dep);
        if (old == NCTA - 1) { g_cnt[0] = 0; g_cnt[1] = 0; g_done = 0; }
    }
    __syncthreads();
    const int c0 = hdr[0], c1 = hdr[1];

    const int t0 = (c0 + 127) >> 7, t1 = (c1 + 127) >> 7;
    const int T = t0 + t1;
    int n0c;
    if (t1 == 0)      n0c = NCTA;
    else if (t0 == 0) n0c = 0;
    else {
        n0c = (int)((long long)NCTA * t0 / T);
        if (n0c < 1) n0c = 1;
        if (n0c > NCTA - 1) n0c = NCTA - 1;
    }

    int e, tbase, tstride, tcnt, cnt;
    if ((int)blockIdx.x < n0c) { e = 0; tbase = blockIdx.x;        tstride = n0c;        tcnt = t0; cnt = c0; }
    else                       { e = 1; tbase = blockIdx.x - n0c;  tstride = NCTA - n0c; tcnt = t1; cnt = c1; }
    const int ntiles = (tbase < tcnt) ? (tcnt - 1 - tbase) / tstride + 1 : 0;
    if (ntiles == 0) return;

    const uint32_t smb = smem_u32(sm_mma);
    float* b1s  = (float*)(sm_mma + SM_B1);
    float* w20  = (float*)(sm_mma + SM_W20);
    float* w21  = (float*)(sm_mma + SM_W21);
    float* outb = (float*)(sm_mma + SM_OUT);

    // ---- A-tile prefetch: 256B fp16 rows from g_xh, 2 threads per row ------
    auto prefetchA = [&](int posbase, int buf) {
        const int row = tid >> 1, segb = (tid & 1) * 8;
        int pos = posbase + row;
        int gi = g_idx[e][(pos < cnt) ? pos : posbase];
        const char* src = (const char*)g_xh + (size_t)gi * 256 + segb * 16;
        uint32_t dst = smb + SM_A + buf * ABUF + row * PITCH + segb * 16;
        #pragma unroll
        for (int j = 0; j < 8; j++) cpasync16(dst + j * 16, src + j * 16);
        CP_COMMIT();
    };

    // ---- prologue: A(tile0) + full W stage + coefficients ------------------
    prefetchA(tbase * 128, 0);
    {
        const char* wsrc = (const char*)(g_w1c + (size_t)e * NH * 128);
        #pragma unroll
        for (int k = 0; k < 32; k++) {                 // 8192 x 16B
            int i = tid + k * 256;
            int row = i >> 4, seg = i & 15;
            cpasync16(smb + SM_W + row * PITCH + seg * 16, wsrc + row * 256 + seg * 16);
        }
        CP_COMMIT();
    }
    for (int i = tid; i < NH; i += 256) {
        b1s[i] = b1[e * NH + i];
        w20[i] = w2[(e * NO + 0) * NH + i];
        w21[i] = w2[(e * NO + 1) * NH + i];
    }
    outb[tid] = 0.f;
    const float b2e0 = b2[e * NO + 0], b2e1 = b2[e * NO + 1];

    CP_WAIT0();
    __syncthreads();

    // ---- per-lane fragment addressing (4m x 2n, warp tile m32 x n64) -------
    const int l  = tid & 31;
    const int w  = tid >> 5;
    const int wm = w & 3;       // m group (32 rows)
    const int wn = w >> 2;      // n half (64 cols)

    uint32_t aRel0, aRel1;
    {
        int mrow = wm * 32 + (l & 7) + ((l >> 3) & 1) * 8;
        int koff = (l >= 16) ? 16 : 0;
        aRel0 = (uint32_t)(mrow * PITCH + koff);
        aRel1 = aRel0 + 16 * PITCH;
    }
    uint32_t bOff[4];
    {
        int nr   = (l & 7) + ((l >= 16) ? 8 : 0);
        int koff = ((l >> 3) & 1) * 16;
        #pragma unroll
        for (int nj = 0; nj < 4; nj++)
            bOff[nj] = (uint32_t)((wn * 64 + nj * 16 + nr) * PITCH + koff);
    }

    // ---- persistent tile loop ----------------------------------------------
    int p = 0;
    for (int it = 0; it < ntiles; it++) {
        const int posbase = (tbase + it * tstride) * 128;
        if (it + 1 < ntiles) prefetchA((tbase + (it + 1) * tstride) * 128, p ^ 1);

        // A fragments: m32 x k128, loaded once, reused across all 4 n-passes
        const uint32_t abase = smb + SM_A + p * ABUF;
        uint32_t areg[8][2][4];
        #pragma unroll
        for (int ks = 0; ks < 8; ks++) {
            ldsm4(areg[ks][0], abase + aRel0 + ks * 32);
            ldsm4(areg[ks][1], abase + aRel1 + ks * 32);
        }

        float o0[4] = {0.f, 0.f, 0.f, 0.f};
        float o1[4] = {0.f, 0.f, 0.f, 0.f};

        #pragma unroll
        for (int nt = 0; nt < 4; nt++) {
            float acc[2][8][4];
            #pragma unroll
            for (int mi = 0; mi < 2; mi++)
                #pragma unroll
                for (int ni = 0; ni < 8; ni++)
                    #pragma unroll
                    for (int c = 0; c < 4; c++) acc[mi][ni][c] = 0.f;

            const uint32_t wbase = smb + SM_W + nt * 128 * PITCH;
            #pragma unroll
            for (int ks = 0; ks < 8; ks++) {
                const int off = ks * 32;
                uint32_t b[4][4];
                #pragma unroll
                for (int nj = 0; nj < 4; nj++)
                    ldsm4(b[nj], wbase + bOff[nj] + off);
                #pragma unroll
                for (int mi = 0; mi < 2; mi++)
                    #pragma unroll
                    for (int nj = 0; nj < 4; nj++) {
                        mma16816(acc[mi][2 * nj],     areg[ks][mi], b[nj][0], b[nj][1]);
                        mma16816(acc[mi][2 * nj + 1], areg[ks][mi], b[nj][2], b[nj][3]);
                    }
            }

            // fused epilogue: +b1, relu, *W2 -> per-lane partials (no barrier)
            const int hbase = nt * 128 + wn * 64 + 2 * (l & 3);
            #pragma unroll
            for (int ni = 0; ni < 8; ni++) {
                const int h = hbase + ni * 8;
                float bq0 = b1s[h],   bq1 = b1s[h + 1];
                float p00 = w20[h],   p01 = w20[h + 1];
                float p10 = w21[h],   p11 = w21[h + 1];
                #pragma unroll
                for (int mi = 0; mi < 2; mi++)
                    #pragma unroll
                    for (int c = 0; c < 4; c++) {
                        float v = acc[mi][ni][c] + ((c & 1) ? bq1 : bq0);
                        v = fmaxf(v, 0.f);
                        int s = mi * 2 + (c >> 1);
                        o0[s] = fmaf(v, (c & 1) ? p01 : p00, o0[s]);
                        o1[s] = fmaf(v, (c & 1) ? p11 : p10, o1[s]);
                    }
            }
        }

        // quad reduce (cols live on l&3), cross-n-warp via smem atomics
        #pragma unroll
        for (int s = 0; s < 4; s++) {
            o0[s] += __shfl_xor_sync(0xffffffffu, o0[s], 1);
            o0[s] += __shfl_xor_sync(0xffffffffu, o0[s], 2);
            o1[s] += __shfl_xor_sync(0xffffffffu, o1[s], 1);
            o1[s] += __shfl_xor_sync(0xffffffffu, o1[s], 2);
        }
        if ((l & 3) == 0) {
            #pragma unroll
            for (int s = 0; s < 4; s++) {
                int row = wm * 32 + (s >> 1) * 16 + (s & 1) * 8 + (l >> 2);
                atomicAdd(&outb[row * 2 + 0], o0[s]);
                atomicAdd(&outb[row * 2 + 1], o1[s]);
            }
        }
        __syncthreads();

        if (tid < 128) {
            int pos = posbase + tid;
            if (pos < cnt) {
                int gi = g_idx[e][pos];
                out[(size_t)gi * 2 + 0] = outb[tid * 2 + 0] + b2e0;
                out[(size_t)gi * 2 + 1] = outb[tid * 2 + 1] + b2e1;
            }
            outb[tid * 2 + 0] = 0.f;     // reader zeroes what it read (no race)
            outb[tid * 2 + 1] = 0.f;
        }

        CP_WAIT0();          // next A tile resident
        __syncthreads();     // outb reset + A buffer handoff visible to all
        p ^= 1;
    }
}

// ---------------- launch ----------------------------------------------------
extern "C" void kernel_launch(void* const* d_in, const int* in_sizes, int n_in,
                              void* d_out, int out_size) {
    const float* x      = (const float*)d_in[0];
    const float* w1     = (const float*)d_in[1];
    const float* b1     = (const float*)d_in[2];
    const float* w2     = (const float*)d_in[3];
    const float* b2     = (const float*)d_in[4];
    const float* protos = (const float*)d_in[5];
    float* out = (float*)d_out;

    static int smem_set = 0;
    if (!smem_set) {
        cudaFuncSetAttribute(mma_kernel, cudaFuncAttributeMaxDynamicSharedMemorySize,
                             SM_TOTAL);
        smem_set = 1;
    }

    route_kernel<<<RB2 + 256, 256>>>(x, protos, w1);   // route + x fp16 + W1 fp16
    mma_kernel<<<NCTA, 256, SM_TOTAL>>>(b1, w2, b2, out);
}